// round 15
// baseline (speedup 1.0000x reference)
#include <cuda_runtime.h>

#define NOUT 48
#define CIN 384
#define NPIX 35200       // 200*176; %32==0
#define NB 4
#define TOTAL_PIX 140800 // = 275 * 512
#define NSTG 24          // CIN / 16 (16 channels per stage)
#define RING 3           // warp-private ring; prefetch distance 2
#define NWARP 16         // 512 threads

#define WSTR 400         // packed-B row stride (floats): 400 mod 32 = 16 -> LDS.128 CF
#define WS_F (NOUT * WSTR)          // 19200
#define BS_OFF WS_F
#define SA_OFF (WS_F + NOUT)        // 19248 floats (*4 = 76992, 16B-aligned)
#define SA_ROW 40                   // 32 px + pad; 40 mod 32 = 8 -> A-frag LDS CF
#define SA_BUF (16 * SA_ROW)        // 640 floats per 16-channel stage buffer
#define SA_WARP (RING * SA_BUF)     // 1920 floats per warp
#define SMEM_FLOATS (SA_OFF + NWARP * SA_WARP)   // 49968 -> 199872 B (1 block/SM)

extern __shared__ float s_buf[];

__device__ __forceinline__ float to_tf32(float x) {
    float r;
    asm("cvt.rna.tf32.f32 %0, %1;" : "=f"(r) : "f"(x));
    return r;
}

__device__ __forceinline__ void mma_tf32(float c[4], const unsigned a[4], unsigned b0, unsigned b1) {
    asm("mma.sync.aligned.m16n8k8.row.col.f32.tf32.tf32.f32 "
        "{%0,%1,%2,%3}, {%4,%5,%6,%7}, {%8,%9}, {%0,%1,%2,%3};"
        : "+f"(c[0]), "+f"(c[1]), "+f"(c[2]), "+f"(c[3])
        : "r"(a[0]), "r"(a[1]), "r"(a[2]), "r"(a[3]), "r"(b0), "r"(b1));
}

__device__ __forceinline__ void cp16(unsigned sdst, const float* gsrc) {
    asm volatile("cp.async.cg.shared.global [%0], [%1], 16;\n"
                 :: "r"(sdst), "l"(gsrc) : "memory");
}
__device__ __forceinline__ void cp_commit() {
    asm volatile("cp.async.commit_group;\n" ::: "memory");
}
template <int N>
__device__ __forceinline__ void cp_wait() {
    asm volatile("cp.async.wait_group %0;\n" :: "n"(N) : "memory");
}

__global__ __launch_bounds__(512, 1)
void proposal_kernel(const float* __restrict__ feat,
                     const float* __restrict__ Wc,
                     const float* __restrict__ bc,
                     const float* __restrict__ Wr,
                     const float* __restrict__ br,
                     float* __restrict__ out)
{
    float* ws = s_buf;                   // packed: ws[o*WSTR + s*16 + tg*4 + j] = tf32(W[o][16s+tg+4j])
    float* bs = s_buf + BS_OFF;

    const int tid  = threadIdx.x;
    const int lane = tid & 31;
    const int warp = tid >> 5;           // 0..15
    const int gid  = lane >> 2;          // 0..7
    const int tg   = lane & 3;           // 0..3

    // warp pixel window (32 px; never crosses batch: NPIX % 32 == 0)
    const int wbase = blockIdx.x * 512 + warp * 32;
    const int bw    = wbase / NPIX;
    const int pw    = wbase % NPIX;

    // staging role: lane = channel (lane&15) x px-half ((lane>>4)*16); 4 cp16/lane/stage
    const int c_l = lane & 15;
    const int ph  = (lane >> 4) * 16;
    float* sa_warp = s_buf + SA_OFF + warp * SA_WARP;
    const unsigned sa_u = (unsigned)__cvta_generic_to_shared(sa_warp);
    const unsigned dst_off = (unsigned)((c_l * SA_ROW + ph) * 4);
    const float* gsrc = feat + (long)bw * CIN * NPIX + (long)c_l * NPIX + pw + ph;

    // ---- prologue: issue stages 0..1 (overlaps weight fill) ----
#pragma unroll
    for (int s = 0; s < RING - 1; s++) {
        const float* g = gsrc + (long)(16 * s) * NPIX;
        const unsigned d = sa_u + (unsigned)(s * SA_BUF * 4) + dst_off;
        cp16(d, g);  cp16(d + 16, g + 4);  cp16(d + 32, g + 8);  cp16(d + 48, g + 12);
        cp_commit();
    }

    // ---- packed weight + bias staging ----
    for (int i = tid; i < NOUT * CIN; i += blockDim.x) {
        const int o  = i / CIN;
        const int kk = i % CIN;
        const int s  = kk >> 4;
        const int t  = kk & 3;
        const int j  = (kk & 15) >> 2;
        ws[o * WSTR + s * 16 + t * 4 + j] = to_tf32((o < 6) ? Wc[o * CIN + kk]
                                                            : Wr[(o - 6) * CIN + kk]);
    }
    if (tid < NOUT) bs[tid] = (tid < 6) ? bc[tid] : br[tid - 6];
    __syncthreads();   // the only block barrier

    // acc[mt][nt][0..3]: c0=(h0,even) c1=(h0,odd) c2=(h1,even) c3=(h1,odd); n=8*nt+2*tg(+1)
    float acc[2][6][4];
#pragma unroll
    for (int nt = 0; nt < 6; nt++) {
        const float be = bs[8 * nt + 2 * tg];
        const float bo = bs[8 * nt + 2 * tg + 1];
#pragma unroll
        for (int mt = 0; mt < 2; mt++) {
            acc[mt][nt][0] = be; acc[mt][nt][1] = bo;
            acc[mt][nt][2] = be; acc[mt][nt][3] = bo;
        }
    }

    // A-fragment row offsets within a stage buffer (bank = 8k+m mod 32, CF)
    const int fA = tg * SA_ROW + gid;            // k = tg
    const int fB = (tg + 4)  * SA_ROW + gid;     // k = tg+4
    const int fC = (tg + 8)  * SA_ROW + gid;     // k = tg+8
    const int fD = (tg + 12) * SA_ROW + gid;     // k = tg+12
    const int wrow = gid * WSTR + tg * 4;        // + 8*nt*WSTR + 16*s per use

    // ---- main loop: warp-private, barrier-free (R13/R14-validated scheme) ----
#pragma unroll 3
    for (int s = 0; s < NSTG; s++) {
        if (s + RING - 1 < NSTG) {
            const float* g = gsrc + (long)(16 * (s + RING - 1)) * NPIX;
            const unsigned d = sa_u +
                (unsigned)((((s + RING - 1) % RING) * SA_BUF) * 4) + dst_off;
            cp16(d, g);  cp16(d + 16, g + 4);  cp16(d + 32, g + 8);  cp16(d + 48, g + 12);
        }
        cp_commit();          // one group per iter (possibly empty) -> exact algebra
        cp_wait<RING - 1>();  // s+RING committed; <=RING-1 pending => stage s ready
        __syncwarp();

        const float* sb = sa_warp + (s % RING) * SA_BUF;
        // octet 0 (k = tg, tg+4), octet 1 (k = tg+8, tg+12); m-tiles 0/1 = px 0..15 / 16..31
        unsigned a00[4], a01[4], a10[4], a11[4];
        a00[0] = __float_as_uint(to_tf32(sb[fA + 0]));
        a00[1] = __float_as_uint(to_tf32(sb[fA + 8]));
        a00[2] = __float_as_uint(to_tf32(sb[fB + 0]));
        a00[3] = __float_as_uint(to_tf32(sb[fB + 8]));
        a10[0] = __float_as_uint(to_tf32(sb[fA + 16]));
        a10[1] = __float_as_uint(to_tf32(sb[fA + 24]));
        a10[2] = __float_as_uint(to_tf32(sb[fB + 16]));
        a10[3] = __float_as_uint(to_tf32(sb[fB + 24]));
        a01[0] = __float_as_uint(to_tf32(sb[fC + 0]));
        a01[1] = __float_as_uint(to_tf32(sb[fC + 8]));
        a01[2] = __float_as_uint(to_tf32(sb[fD + 0]));
        a01[3] = __float_as_uint(to_tf32(sb[fD + 8]));
        a11[0] = __float_as_uint(to_tf32(sb[fC + 16]));
        a11[1] = __float_as_uint(to_tf32(sb[fC + 24]));
        a11[2] = __float_as_uint(to_tf32(sb[fD + 16]));
        a11[3] = __float_as_uint(to_tf32(sb[fD + 24]));

#pragma unroll
        for (int nt = 0; nt < 6; nt++) {
            // one LDS.128: {W[o][k0+tg], W[o][k0+tg+4], W[o][k0+tg+8], W[o][k0+tg+12]}
            const float4 w4 = *(const float4*)(ws + wrow + nt * (8 * WSTR) + s * 16);
            const unsigned bx = __float_as_uint(w4.x), by = __float_as_uint(w4.y);
            const unsigned bz = __float_as_uint(w4.z), bw_ = __float_as_uint(w4.w);
            mma_tf32(acc[0][nt], a00, bx, by);
            mma_tf32(acc[1][nt], a10, bx, by);
            mma_tf32(acc[0][nt], a01, bz, bw_);
            mma_tf32(acc[1][nt], a11, bz, bw_);
        }
    }

    // ================= epilogue (validated since R6) =================
    // pixel = pw + mt*16 + h*8 + gid; pair Q = 4*nt + tg -> outputs (2Q, 2Q+1); even->y0, odd->y1
    float* outr = out + (long)NB * 6 * NPIX;
#pragma unroll
    for (int mt = 0; mt < 2; mt++) {
#pragma unroll
        for (int h = 0; h < 2; h++) {
            const int p = pw + mt * 16 + h * 8 + gid;
#pragma unroll
            for (int nt = 0; nt < 6; nt++) {
                const float ve = acc[mt][nt][2 * h + 0];
                const float vo = acc[mt][nt][2 * h + 1];
                const int Q = 4 * nt + tg;
                if (Q < 3) {
                    out[((long)bw * 6 + 2 * Q + 0) * NPIX + p] = ve;
                    out[((long)bw * 6 + 2 * Q + 1) * NPIX + p] = vo;
                } else {
                    const int r  = Q - 3;
                    const int c3 = r / 7;
                    const int d  = r % 7;
                    outr[((((long)bw * 3 + c3) * 2 + 0) * NPIX + p) * 7 + d] = ve;
                    outr[((((long)bw * 3 + c3) * 2 + 1) * NPIX + p) * 7 + d] = vo;
                }
            }
        }
    }
}

extern "C" void kernel_launch(void* const* d_in, const int* in_sizes, int n_in,
                              void* d_out, int out_size)
{
    const float* feat = (const float*)d_in[0];
    const float* Wc   = (const float*)d_in[1];
    const float* bc   = (const float*)d_in[2];
    const float* Wr   = (const float*)d_in[3];
    const float* br   = (const float*)d_in[4];
    float* out = (float*)d_out;

    const int smem_bytes = SMEM_FLOATS * (int)sizeof(float);   // 199872 B
    cudaFuncSetAttribute(proposal_kernel,
                         cudaFuncAttributeMaxDynamicSharedMemorySize, smem_bytes);

    const int threads = 512;                 // 16 warps x 32 px
    const int blocks  = TOTAL_PIX / 512;     // 275, exact
    proposal_kernel<<<blocks, threads, smem_bytes>>>(feat, Wc, bc, Wr, br, out);
}

// round 16
// speedup vs baseline: 1.0629x; 1.0629x over previous
#include <cuda_runtime.h>

#define NOUT 48
#define CIN 384
#define NPIX 35200       // 200*176; %32==0
#define NB 4
#define TOTAL_PIX 140800 // = 275 * 512
#define NSTAGE 48        // CIN / 8
#define RING 7           // warp-private ring; 2 stages processed per wait
#define NWARP 16         // 512 threads

#define WSTR 388         // ws row stride [o][k]: 388 mod 32 = 4 -> B-frag bank CF
#define WS_F (NOUT * WSTR)          // 18624
#define BS_OFF WS_F
#define SA_OFF (WS_F + NOUT + 8)    // 18680 floats (16B-aligned *4)
#define SA_ROW 40                   // 32 px + pad; LDS.64 pair-bank CF (see fr notes)
#define SA_BUF (8 * SA_ROW)         // 320 floats per 8-channel stage buffer
#define SA_WARP (RING * SA_BUF)     // 2240 floats per warp
#define SMEM_FLOATS (SA_OFF + NWARP * SA_WARP)   // 54520 -> 218080 B (1 block/SM)

extern __shared__ float s_buf[];

__device__ __forceinline__ float to_tf32(float x) {
    float r;
    asm("cvt.rna.tf32.f32 %0, %1;" : "=f"(r) : "f"(x));
    return r;
}

__device__ __forceinline__ void mma_tf32(float c[4], const unsigned a[4], unsigned b0, unsigned b1) {
    asm("mma.sync.aligned.m16n8k8.row.col.f32.tf32.tf32.f32 "
        "{%0,%1,%2,%3}, {%4,%5,%6,%7}, {%8,%9}, {%0,%1,%2,%3};"
        : "+f"(c[0]), "+f"(c[1]), "+f"(c[2]), "+f"(c[3])
        : "r"(a[0]), "r"(a[1]), "r"(a[2]), "r"(a[3]), "r"(b0), "r"(b1));
}

__device__ __forceinline__ void cp16(unsigned sdst, const float* gsrc) {
    asm volatile("cp.async.cg.shared.global [%0], [%1], 16;\n"
                 :: "r"(sdst), "l"(gsrc) : "memory");
}
__device__ __forceinline__ void cp_commit() {
    asm volatile("cp.async.commit_group;\n" ::: "memory");
}
template <int N>
__device__ __forceinline__ void cp_wait() {
    asm volatile("cp.async.wait_group %0;\n" :: "n"(N) : "memory");
}

__global__ __launch_bounds__(512, 1)
void proposal_kernel(const float* __restrict__ feat,
                     const float* __restrict__ Wc,
                     const float* __restrict__ bc,
                     const float* __restrict__ Wr,
                     const float* __restrict__ br,
                     float* __restrict__ out)
{
    float* ws = s_buf;                   // ws[o*WSTR + k] = tf32(W[o][k])
    float* bs = s_buf + BS_OFF;

    const int tid  = threadIdx.x;
    const int lane = tid & 31;
    const int warp = tid >> 5;           // 0..15
    const int gid  = lane >> 2;          // 0..7
    const int tg   = lane & 3;           // 0..3

    // warp pixel window (32 px; never crosses batch: NPIX % 32 == 0)
    const int wbase = blockIdx.x * 512 + warp * 32;
    const int bw    = wbase / NPIX;
    const int pw    = wbase % NPIX;

    // warp-private staging: lane role = channel gid x 8-px chunk tg
    const int pq  = tg * 8;
    float* sa_warp = s_buf + SA_OFF + warp * SA_WARP;
    const unsigned sa_u = (unsigned)__cvta_generic_to_shared(sa_warp);
    const unsigned dst_off = (unsigned)((gid * SA_ROW + pq) * 4);
    const float* gsrc = feat + (long)bw * CIN * NPIX + (long)gid * NPIX + pw + pq;

    // ---- prologue: issue stages 0..4 ----
#pragma unroll
    for (int s = 0; s < RING - 2; s++) {
        const float* g = gsrc + (long)(8 * s) * NPIX;
        const unsigned d = sa_u + (unsigned)(s * SA_BUF * 4) + dst_off;
        cp16(d, g);
        cp16(d + 16, g + 4);
        cp_commit();
    }

    // ---- weight + bias staging ([o][k], validated) ----
    for (int i = tid; i < NOUT * CIN; i += blockDim.x) {
        const int o = i / CIN;
        const int k = i % CIN;
        ws[o * WSTR + k] = to_tf32((o < 6) ? Wc[o * CIN + k] : Wr[(o - 6) * CIN + k]);
    }
    if (tid < NOUT) bs[tid] = (tid < 6) ? bc[tid] : br[tid - 6];
    __syncthreads();   // only block barrier

    // acc[mt][nt][0..3]: c0=(h0,even) c1=(h0,odd) c2=(h1,even) c3=(h1,odd); n=8*nt+2*tg(+1)
    float acc[2][6][4];
#pragma unroll
    for (int nt = 0; nt < 6; nt++) {
        const float be = bs[8 * nt + 2 * tg];
        const float bo = bs[8 * nt + 2 * tg + 1];
#pragma unroll
        for (int mt = 0; mt < 2; mt++) {
            acc[mt][nt][0] = be; acc[mt][nt][1] = bo;
            acc[mt][nt][2] = be; acc[mt][nt][3] = bo;
        }
    }

    const unsigned* wsu = (const unsigned*)ws;
    // NEW bijection: fragment row (mt, h-reg, gid) -> local pixel mt*16 + 2*gid + h
    //   a0 (row gid) and a1 (row gid+8) = adjacent pixels -> one LDS.64 (float2)
    // LDS.64 CF: pair-index = (k*40 + mt*16 + 2*gid)/2 mod 16 = 4*tg + gid + 8*mt, distinct per phase
    const int f00 = tg * SA_ROW + 2 * gid;           // k=tg,   mt=0
    const int f40 = (tg + 4) * SA_ROW + 2 * gid;     // k=tg+4, mt=0
    const int wo  = gid * WSTR;                      // B row base: o = 8*nt + gid

#define COMPUTE_STAGE(K0, BUF)                                                 \
    do {                                                                       \
        const float* sb = sa_warp + (BUF) * SA_BUF;                            \
        const float2 p00 = *(const float2*)(sb + f00);        /* mt0, k=tg   */\
        const float2 p40 = *(const float2*)(sb + f40);        /* mt0, k=tg+4 */\
        const float2 p01 = *(const float2*)(sb + f00 + 16);   /* mt1, k=tg   */\
        const float2 p41 = *(const float2*)(sb + f40 + 16);   /* mt1, k=tg+4 */\
        unsigned a0[4], a1[4];                                                 \
        a0[0] = __float_as_uint(to_tf32(p00.x));                               \
        a0[1] = __float_as_uint(to_tf32(p00.y));                               \
        a0[2] = __float_as_uint(to_tf32(p40.x));                               \
        a0[3] = __float_as_uint(to_tf32(p40.y));                               \
        a1[0] = __float_as_uint(to_tf32(p01.x));                               \
        a1[1] = __float_as_uint(to_tf32(p01.y));                               \
        a1[2] = __float_as_uint(to_tf32(p41.x));                               \
        a1[3] = __float_as_uint(to_tf32(p41.y));                               \
        const int k0 = (K0);                                                   \
        _Pragma("unroll")                                                      \
        for (int nt = 0; nt < 6; nt++) {                                       \
            const unsigned b0 = wsu[wo + nt * (8 * WSTR) + k0 + tg];           \
            const unsigned b1 = wsu[wo + nt * (8 * WSTR) + k0 + tg + 4];       \
            mma_tf32(acc[0][nt], a0, b0, b1);                                  \
            mma_tf32(acc[1][nt], a1, b0, b1);                                  \
        }                                                                      \
    } while (0)

    // ---- main loop: 2 stages per wait; warp-private, barrier-free ----
    int rb = 0;          // buffer of stage s
    int wb = RING - 2;   // buffer of stage s+5
#pragma unroll 2
    for (int s = 0; s < NSTAGE; s += 2) {
        const int wb1 = (wb + 1 == RING) ? 0 : wb + 1;
        if (s + RING - 2 < NSTAGE) {
            const float* g = gsrc + (long)(8 * (s + RING - 2)) * NPIX;
            const unsigned d = sa_u + (unsigned)(wb * SA_BUF * 4) + dst_off;
            cp16(d, g);
            cp16(d + 16, g + 4);
        }
        cp_commit();
        if (s + RING - 1 < NSTAGE) {
            const float* g = gsrc + (long)(8 * (s + RING - 1)) * NPIX;
            const unsigned d = sa_u + (unsigned)(wb1 * SA_BUF * 4) + dst_off;
            cp16(d, g);
            cp16(d + 16, g + 4);
        }
        cp_commit();
        cp_wait<RING - 2>();     // s+7 groups committed; <=5 pending => stages s,s+1 ready
        __syncwarp();

        const int rb1 = (rb + 1 == RING) ? 0 : rb + 1;
        COMPUTE_STAGE(8 * s, rb);
        COMPUTE_STAGE(8 * (s + 1), rb1);

        rb += 2; if (rb >= RING) rb -= RING;
        wb += 2; if (wb >= RING) wb -= RING;
    }

    // ================= epilogue (validated mapping, new pixel formula) =================
    // pixel = pw + mt*16 + 2*gid + h; pair Q = 4*nt + tg -> outputs (2Q, 2Q+1); even->y0, odd->y1
    float* outr = out + (long)NB * 6 * NPIX;
#pragma unroll
    for (int mt = 0; mt < 2; mt++) {
#pragma unroll
        for (int h = 0; h < 2; h++) {
            const int p = pw + mt * 16 + 2 * gid + h;
#pragma unroll
            for (int nt = 0; nt < 6; nt++) {
                const float ve = acc[mt][nt][2 * h + 0];
                const float vo = acc[mt][nt][2 * h + 1];
                const int Q = 4 * nt + tg;
                if (Q < 3) {
                    out[((long)bw * 6 + 2 * Q + 0) * NPIX + p] = ve;
                    out[((long)bw * 6 + 2 * Q + 1) * NPIX + p] = vo;
                } else {
                    const int r  = Q - 3;
                    const int c3 = r / 7;
                    const int d  = r % 7;
                    outr[((((long)bw * 3 + c3) * 2 + 0) * NPIX + p) * 7 + d] = ve;
                    outr[((((long)bw * 3 + c3) * 2 + 1) * NPIX + p) * 7 + d] = vo;
                }
            }
        }
    }
#undef COMPUTE_STAGE
}

extern "C" void kernel_launch(void* const* d_in, const int* in_sizes, int n_in,
                              void* d_out, int out_size)
{
    const float* feat = (const float*)d_in[0];
    const float* Wc   = (const float*)d_in[1];
    const float* bc   = (const float*)d_in[2];
    const float* Wr   = (const float*)d_in[3];
    const float* br   = (const float*)d_in[4];
    float* out = (float*)d_out;

    const int smem_bytes = SMEM_FLOATS * (int)sizeof(float);   // 218080 B
    cudaFuncSetAttribute(proposal_kernel,
                         cudaFuncAttributeMaxDynamicSharedMemorySize, smem_bytes);

    const int threads = 512;                 // 16 warps x 32 px
    const int blocks  = TOTAL_PIX / 512;     // 275, exact
    proposal_kernel<<<blocks, threads, smem_bytes>>>(feat, Wc, bc, Wr, br, out);
}

// round 17
// speedup vs baseline: 1.1343x; 1.0672x over previous
#include <cuda_runtime.h>

#define NOUT 48
#define CIN 384
#define NPIX 35200       // 200*176; %32==0
#define NB 4
#define TOTAL_PIX 140800 // = 275 * 512
#define NSTAGE 48        // CIN / 8
#define RING 6           // warp-private ring; prefetch distance 5 (R14-validated)
#define NWARP 16         // 512 threads

#define WSTR 388         // ws row stride [o][k]: 388 mod 32 = 4 -> B-frag bank CF
#define WS_F (NOUT * WSTR)          // 18624
#define BS_OFF WS_F
#define SA_OFF (WS_F + NOUT + 8)    // 18680 floats (16B-aligned *4)
#define SA_ROW 40                   // 32 px + pad; 40 mod 32 = 8 -> A-frag LDS CF
#define SA_BUF (8 * SA_ROW)         // 320 floats per stage buffer
#define SA_WARP (RING * SA_BUF)     // 1920 floats per warp
#define SMEM_FLOATS (SA_OFF + NWARP * SA_WARP)   // 49400 -> 197600 B (1 block/SM)

extern __shared__ float s_buf[];

__device__ __forceinline__ float to_tf32(float x) {
    float r;
    asm("cvt.rna.tf32.f32 %0, %1;" : "=f"(r) : "f"(x));
    return r;
}

__device__ __forceinline__ void mma_tf32(float c[4], const unsigned a[4], unsigned b0, unsigned b1) {
    asm("mma.sync.aligned.m16n8k8.row.col.f32.tf32.tf32.f32 "
        "{%0,%1,%2,%3}, {%4,%5,%6,%7}, {%8,%9}, {%0,%1,%2,%3};"
        : "+f"(c[0]), "+f"(c[1]), "+f"(c[2]), "+f"(c[3])
        : "r"(a[0]), "r"(a[1]), "r"(a[2]), "r"(a[3]), "r"(b0), "r"(b1));
}

__device__ __forceinline__ void cp16(unsigned sdst, const float* gsrc) {
    asm volatile("cp.async.cg.shared.global [%0], [%1], 16;\n"
                 :: "r"(sdst), "l"(gsrc) : "memory");
}
__device__ __forceinline__ void cp_commit() {
    asm volatile("cp.async.commit_group;\n" ::: "memory");
}
template <int N>
__device__ __forceinline__ void cp_wait() {
    asm volatile("cp.async.wait_group %0;\n" :: "n"(N) : "memory");
}

__global__ __launch_bounds__(512, 1)
void proposal_kernel(const float* __restrict__ feat,
                     const float* __restrict__ Wc,
                     const float* __restrict__ bc,
                     const float* __restrict__ Wr,
                     const float* __restrict__ br,
                     float* __restrict__ out)
{
    float* ws = s_buf;                   // ws[o*WSTR + k] = tf32(W[o][k])
    float* bs = s_buf + BS_OFF;

    const int tid  = threadIdx.x;
    const int lane = tid & 31;
    const int warp = tid >> 5;           // 0..15
    const int gid  = lane >> 2;          // 0..7
    const int tg   = lane & 3;           // 0..3

    // warp pixel window (32 px; never crosses batch: NPIX % 32 == 0)
    const int wbase = blockIdx.x * 512 + warp * 32;
    const int bw    = wbase / NPIX;
    const int pw    = wbase % NPIX;

    // warp-private staging: lane role = channel gid (0..7) x 8-px chunk tg (0..3)
    const int pq  = tg * 8;
    float* sa_warp = s_buf + SA_OFF + warp * SA_WARP;
    const unsigned sa_u = (unsigned)__cvta_generic_to_shared(sa_warp);
    const unsigned dst_off = (unsigned)((gid * SA_ROW + pq) * 4);
    const float* gsrc = feat + (long)bw * CIN * NPIX + (long)gid * NPIX + pw + pq;

    // ---- prologue: issue stages 0..RING-2 (overlaps with weight fill) ----
#pragma unroll
    for (int s = 0; s < RING - 1; s++) {
        const float* g = gsrc + (long)(8 * s) * NPIX;
        const unsigned d = sa_u + (unsigned)(s * SA_BUF * 4) + dst_off;
        cp16(d, g);
        cp16(d + 16, g + 4);
        cp_commit();
    }

    // ---- weight + bias staging ([o][k], validated since R11) ----
    for (int i = tid; i < NOUT * CIN; i += blockDim.x) {
        const int o = i / CIN;
        const int k = i % CIN;
        ws[o * WSTR + k] = to_tf32((o < 6) ? Wc[o * CIN + k] : Wr[(o - 6) * CIN + k]);
    }
    if (tid < NOUT) bs[tid] = (tid < 6) ? bc[tid] : br[tid - 6];
    __syncthreads();   // the only block barrier in the kernel

    // acc[mt][nt][0..3]: c0=(h0,even) c1=(h0,odd) c2=(h1,even) c3=(h1,odd); n=8*nt+2*tg(+1)
    float acc[2][6][4];
#pragma unroll
    for (int nt = 0; nt < 6; nt++) {
        const float be = bs[8 * nt + 2 * tg];
        const float bo = bs[8 * nt + 2 * tg + 1];
#pragma unroll
        for (int mt = 0; mt < 2; mt++) {
            acc[mt][nt][0] = be; acc[mt][nt][1] = bo;
            acc[mt][nt][2] = be; acc[mt][nt][3] = bo;
        }
    }

    const unsigned* wsu = (const unsigned*)ws;
    // A-fragment offsets (R14 mapping: px = mt*16 + h*8 + gid; bank = 8k+m mod 32, CF)
    const int fr0 = tg * SA_ROW + gid;        // k=tg
    const int fr4 = (tg + 4) * SA_ROW + gid;  // k=tg+4
    const int wo  = gid * WSTR;               // B row base: o = 8*nt + gid

#define LOAD_FRAGS(A0, A1, BUF)                                                \
    do {                                                                       \
        const float* sb = sa_warp + (BUF) * SA_BUF;                            \
        (A0)[0] = __float_as_uint(to_tf32(sb[fr0 + 0]));                       \
        (A0)[1] = __float_as_uint(to_tf32(sb[fr0 + 8]));                       \
        (A0)[2] = __float_as_uint(to_tf32(sb[fr4 + 0]));                       \
        (A0)[3] = __float_as_uint(to_tf32(sb[fr4 + 8]));                       \
        (A1)[0] = __float_as_uint(to_tf32(sb[fr0 + 16]));                      \
        (A1)[1] = __float_as_uint(to_tf32(sb[fr0 + 24]));                      \
        (A1)[2] = __float_as_uint(to_tf32(sb[fr4 + 16]));                      \
        (A1)[3] = __float_as_uint(to_tf32(sb[fr4 + 24]));                      \
    } while (0)

    // ---- fragment double-buffer: wait for stage 0, preload its frags ----
    unsigned curA0[4], curA1[4], nxtA0[4], nxtA1[4];
    cp_wait<RING - 2>();    // RING-1 groups committed; <=RING-2 pending => stage 0 ready
    __syncwarp();
    LOAD_FRAGS(curA0, curA1, 0);

    // ---- main loop (R14 pipeline + register prefetch of stage s+1 frags) ----
    // At iter s: groups committed = s+RING; wait<RING-2> => >= s+2 complete => s+1 ready.
    // WAR: write buf (s+RING-1)%RING = (s-1)%RING, whose frags were read at iter s-2.
#pragma unroll 6
    for (int s = 0; s < NSTAGE; s++) {
        if (s + RING - 1 < NSTAGE) {
            const float* g = gsrc + (long)(8 * (s + RING - 1)) * NPIX;
            const unsigned d = sa_u +
                (unsigned)((((s + RING - 1) % RING) * SA_BUF) * 4) + dst_off;
            cp16(d, g);
            cp16(d + 16, g + 4);
        }
        cp_commit();            // one group per iter (possibly empty) -> exact algebra
        cp_wait<RING - 2>();
        __syncwarp();

        if (s + 1 < NSTAGE)
            LOAD_FRAGS(nxtA0, nxtA1, (s + 1) % RING);   // overlaps with MMAs below

        const int k0 = 8 * s;
#pragma unroll
        for (int nt = 0; nt < 6; nt++) {
            const unsigned b0 = wsu[wo + nt * (8 * WSTR) + k0 + tg];      // CF LDS
            const unsigned b1 = wsu[wo + nt * (8 * WSTR) + k0 + tg + 4];
            mma_tf32(acc[0][nt], curA0, b0, b1);
            mma_tf32(acc[1][nt], curA1, b0, b1);
        }

#pragma unroll
        for (int j = 0; j < 4; j++) { curA0[j] = nxtA0[j]; curA1[j] = nxtA1[j]; }
    }
#undef LOAD_FRAGS

    // ================= epilogue (validated since R6) =================
    // pixel = pw + mt*16 + h*8 + gid; pair Q = 4*nt + tg -> outputs (2Q, 2Q+1); even->y0, odd->y1
    float* outr = out + (long)NB * 6 * NPIX;
#pragma unroll
    for (int mt = 0; mt < 2; mt++) {
#pragma unroll
        for (int h = 0; h < 2; h++) {
            const int p = pw + mt * 16 + h * 8 + gid;
#pragma unroll
            for (int nt = 0; nt < 6; nt++) {
                const float ve = acc[mt][nt][2 * h + 0];
                const float vo = acc[mt][nt][2 * h + 1];
                const int Q = 4 * nt + tg;
                if (Q < 3) {
                    out[((long)bw * 6 + 2 * Q + 0) * NPIX + p] = ve;
                    out[((long)bw * 6 + 2 * Q + 1) * NPIX + p] = vo;
                } else {
                    const int r  = Q - 3;
                    const int c3 = r / 7;
                    const int d  = r % 7;
                    outr[((((long)bw * 3 + c3) * 2 + 0) * NPIX + p) * 7 + d] = ve;
                    outr[((((long)bw * 3 + c3) * 2 + 1) * NPIX + p) * 7 + d] = vo;
                }
            }
        }
    }
}

extern "C" void kernel_launch(void* const* d_in, const int* in_sizes, int n_in,
                              void* d_out, int out_size)
{
    const float* feat = (const float*)d_in[0];
    const float* Wc   = (const float*)d_in[1];
    const float* bc   = (const float*)d_in[2];
    const float* Wr   = (const float*)d_in[3];
    const float* br   = (const float*)d_in[4];
    float* out = (float*)d_out;

    const int smem_bytes = SMEM_FLOATS * (int)sizeof(float);   // 197600 B
    cudaFuncSetAttribute(proposal_kernel,
                         cudaFuncAttributeMaxDynamicSharedMemorySize, smem_bytes);

    const int threads = 512;                 // 16 warps x 32 px
    const int blocks  = TOTAL_PIX / 512;     // 275, exact
    proposal_kernel<<<blocks, threads, smem_bytes>>>(feat, Wc, bc, Wr, br, out);
}